// round 4
// baseline (speedup 1.0000x reference)
#include <cuda_runtime.h>
#include <cuda_bf16.h>

#define B_  32
#define C_  256
#define HW_ 64
#define AS_ 8
#define T_  64    // AS*AS
#define CT_ (C_ * T_)

typedef unsigned long long ull;

__device__ __forceinline__ ull pack2(float lo, float hi) {
    ull r; asm("mov.b64 %0, {%1, %2};" : "=l"(r) : "f"(lo), "f"(hi)); return r;
}
__device__ __forceinline__ void unpack2(float& lo, float& hi, ull v) {
    asm("mov.b64 {%0, %1}, %2;" : "=f"(lo), "=f"(hi) : "l"(v));
}
__device__ __forceinline__ void fma2(ull& d, ull a, ull b) {
    asm("fma.rn.f32x2 %0, %1, %2, %0;" : "+l"(d) : "l"(a), "l"(b));
}

// ---------------- scratch (device globals; batch-major [b][c][t]) ----------------
__device__ float g_PR[B_ * CT_];
__device__ float g_PD[B_ * CT_];
__device__ float g_Q [B_ * CT_];
__device__ float g_K [B_ * CT_];
__device__ float g_V [B_ * CT_];
__device__ float g_Apart[4 * B_ * T_ * T_];  // 4 c-slices of 64
__device__ float g_F [B_ * CT_];

// ---------------- 1) 8x8 avg pool (F_d first, F_rgb last for L2 residency) ----------------
__global__ void pool_kernel(const float* __restrict__ Frgb, const float* __restrict__ Fd) {
    int bid   = blockIdx.x;
    int which = bid >> 13;
    int plane = bid & 8191;
    const float* src = (which ? Frgb : Fd) + (size_t)plane * (HW_ * HW_);
    float* dst = (which ? g_PR : g_PD) + (size_t)plane * T_;

    __shared__ float part[128];
    int t = threadIdx.x;
    int chunk = t & 15;
    int i     = t >> 4;
    const float4* p = (const float4*)src;
    float s = 0.f;
#pragma unroll
    for (int r = 0; r < 8; r++) {
        float4 v = p[(i * 8 + r) * 16 + chunk];
        s += (v.x + v.y) + (v.z + v.w);
    }
    part[t] = s;
    __syncthreads();
    if (t < 64) {
        int pi = t >> 3, pj = t & 7;
        dst[t] = (part[pi * 16 + 2 * pj] + part[pi * 16 + 2 * pj + 1]) * (1.0f / 64.0f);
    }
}

// ---------------- 2) QKV: zero-MOV f32x2. grid (B,4,3), 256 thr, 4m x 4n per thread --------
__global__ void qkv_kernel(const float* __restrict__ Wq, const float* __restrict__ bq,
                           const float* __restrict__ Wk, const float* __restrict__ bk,
                           const float* __restrict__ Wv, const float* __restrict__ bv) {
    int b  = blockIdx.x;
    int o0 = blockIdx.y * 64;
    int z  = blockIdx.z;
    const float* W; const float* bias; const float* P; float* Out;
    if (z == 0)      { W = Wq; bias = bq; P = g_PR; Out = g_Q; }
    else if (z == 1) { W = Wk; bias = bk; P = g_PD; Out = g_K; }
    else             { W = Wv; bias = bv; P = g_PD; Out = g_V; }

    __shared__ float Wst[32][68];    // transposed [k][m] (m contiguous -> ull m-pairs)
    __shared__ float Xsd[32][128];   // duplicated [k][2n] = (x,x)

    int tid = threadIdx.x;
    int m0 = (tid >> 4) * 4;
    int n0 = (tid & 15) * 4;
    const float* Pb = P + ((size_t)b * CT_);

    ull acc[2][4];
#pragma unroll
    for (int p = 0; p < 2; p++)
#pragma unroll
        for (int j = 0; j < 4; j++) acc[p][j] = 0ull;

    for (int kc = 0; kc < C_; kc += 32) {
        // W tile [64m][32k] -> Wst[k][m]
#pragma unroll
        for (int q = 0; q < 2; q++) {
            int l = tid + q * 256;
            int row = l >> 3, c4 = l & 7;
            float4 v = *(const float4*)&W[(o0 + row) * C_ + kc + c4 * 4];
            Wst[c4 * 4 + 0][row] = v.x; Wst[c4 * 4 + 1][row] = v.y;
            Wst[c4 * 4 + 2][row] = v.z; Wst[c4 * 4 + 3][row] = v.w;
        }
        // X tile [32k][64t] -> duplicated Xsd[k][2t]
#pragma unroll
        for (int q = 0; q < 2; q++) {
            int l = tid + q * 256;
            int row = l >> 4, c4 = l & 15;
            float4 v = *(const float4*)&Pb[(size_t)(kc + row) * T_ + c4 * 4];
            ull* dp = (ull*)&Xsd[row][c4 * 8];
            dp[0] = pack2(v.x, v.x); dp[1] = pack2(v.y, v.y);
            dp[2] = pack2(v.z, v.z); dp[3] = pack2(v.w, v.w);
        }
        __syncthreads();
#pragma unroll
        for (int k = 0; k < 32; k++) {
            float4 av = *(const float4*)&Wst[k][m0];     // (W[m0][k],W[m0+1][k],W[m0+2][k],W[m0+3][k])
            ull a0 = ((const ull*)&av)[0];                // m-pair (m0, m0+1)
            ull a1 = ((const ull*)&av)[1];                // m-pair (m0+2, m0+3)
            const ull* bp = (const ull*)&Xsd[k][n0 * 2];  // 4 dup ulls (32B) via 2 LDS.128
            ull b0 = bp[0], b1 = bp[1], b2 = bp[2], b3 = bp[3];
            fma2(acc[0][0], a0, b0); fma2(acc[0][1], a0, b1);
            fma2(acc[0][2], a0, b2); fma2(acc[0][3], a0, b3);
            fma2(acc[1][0], a1, b0); fma2(acc[1][1], a1, b1);
            fma2(acc[1][2], a1, b2); fma2(acc[1][3], a1, b3);
        }
        __syncthreads();
    }

    float* Ob = Out + ((size_t)b * CT_);
#pragma unroll
    for (int p = 0; p < 2; p++) {
        float lo[4], hi[4];
#pragma unroll
        for (int j = 0; j < 4; j++) unpack2(lo[j], hi[j], acc[p][j]);
        int mlo = o0 + m0 + 2 * p, mhi = mlo + 1;
        float blo = bias[mlo], bhi = bias[mhi];
        *(float4*)&Ob[(size_t)mlo * T_ + n0] =
            make_float4(lo[0] + blo, lo[1] + blo, lo[2] + blo, lo[3] + blo);
        *(float4*)&Ob[(size_t)mhi * T_ + n0] =
            make_float4(hi[0] + bhi, hi[1] + bhi, hi[2] + bhi, hi[3] + bhi);
    }
}

// ---------------- 3) partial A: grid (B,4), 256 thr, 4t x 4s, zero-MOV f32x2 --------------
__global__ void attn_partial_kernel() {
    int b  = blockIdx.x;
    int c0 = blockIdx.y * 64;
    __shared__ float Qs[64][64];     // [k][t] natural (t contiguous -> t-pairs)
    __shared__ float Ksd[64][128];   // duplicated [k][2s]
    int tid = threadIdx.x;
    const float* Qb = g_Q + ((size_t)b * CT_) + (size_t)c0 * T_;
    const float* Kb = g_K + ((size_t)b * CT_) + (size_t)c0 * T_;
#pragma unroll
    for (int q = 0; q < 4; q++) {
        int l = tid + q * 256;
        int row = l >> 4, c4 = l & 15;
        *(float4*)&Qs[row][c4 * 4] = *(const float4*)&Qb[(size_t)row * T_ + c4 * 4];
        float4 v = *(const float4*)&Kb[(size_t)row * T_ + c4 * 4];
        ull* dp = (ull*)&Ksd[row][c4 * 8];
        dp[0] = pack2(v.x, v.x); dp[1] = pack2(v.y, v.y);
        dp[2] = pack2(v.z, v.z); dp[3] = pack2(v.w, v.w);
    }
    __syncthreads();
    int m0 = (tid >> 4) * 4;   // t
    int n0 = (tid & 15) * 4;   // s
    ull acc[2][4];
#pragma unroll
    for (int p = 0; p < 2; p++)
#pragma unroll
        for (int j = 0; j < 4; j++) acc[p][j] = 0ull;
#pragma unroll
    for (int k = 0; k < 64; k++) {
        float4 av = *(const float4*)&Qs[k][m0];
        ull a0 = ((const ull*)&av)[0];
        ull a1 = ((const ull*)&av)[1];
        const ull* bp = (const ull*)&Ksd[k][n0 * 2];
        ull b0 = bp[0], b1 = bp[1], b2 = bp[2], b3 = bp[3];
        fma2(acc[0][0], a0, b0); fma2(acc[0][1], a0, b1);
        fma2(acc[0][2], a0, b2); fma2(acc[0][3], a0, b3);
        fma2(acc[1][0], a1, b0); fma2(acc[1][1], a1, b1);
        fma2(acc[1][2], a1, b2); fma2(acc[1][3], a1, b3);
    }
    float* Ap = g_Apart + (((size_t)blockIdx.y * B_ + b) * (T_ * T_));
#pragma unroll
    for (int p = 0; p < 2; p++) {
        float lo[4], hi[4];
#pragma unroll
        for (int j = 0; j < 4; j++) unpack2(lo[j], hi[j], acc[p][j]);
        *(float4*)&Ap[(m0 + 2 * p) * T_ + n0]     = make_float4(lo[0], lo[1], lo[2], lo[3]);
        *(float4*)&Ap[(m0 + 2 * p + 1) * T_ + n0] = make_float4(hi[0], hi[1], hi[2], hi[3]);
    }
}

// ---------------- 4) fused: reduce partials + softmax (redundant per block) + Fatt slice ----
// grid (B, 8 chunks of 32 channels), 256 threads.
__global__ void softmax_fatt_kernel() {
    int b = blockIdx.x, cc = blockIdx.y;
    __shared__ float Ast[64][68];    // transposed softmaxed A: [s][t] (t contiguous -> t-pairs)
    __shared__ float Vsd[32][130];   // duplicated [c][2s], padded
    int tid = threadIdx.x;
    int warp = tid >> 5, lane = tid & 31;

    // --- softmax of summed partials, written transposed into Ast[s][t] ---
#pragma unroll
    for (int rr = 0; rr < 8; rr++) {
        int r = warp * 8 + rr;                       // t-row
        size_t base = (size_t)b * (T_ * T_) + r * T_;
        float v0 = 0.f, v1 = 0.f;
#pragma unroll
        for (int p = 0; p < 4; p++) {
            size_t pb = ((size_t)p * B_) * (T_ * T_) + base;
            v0 += g_Apart[pb + lane];
            v1 += g_Apart[pb + lane + 32];
        }
        float m = fmaxf(v0, v1);
#pragma unroll
        for (int off = 16; off; off >>= 1) m = fmaxf(m, __shfl_xor_sync(0xffffffffu, m, off));
        float e0 = __expf(v0 - m), e1 = __expf(v1 - m);
        float s = e0 + e1;
#pragma unroll
        for (int off = 16; off; off >>= 1) s += __shfl_xor_sync(0xffffffffu, s, off);
        float inv = 1.0f / s;
        Ast[lane][r]      = e0 * inv;                // A[t=r][s=lane]
        Ast[lane + 32][r] = e1 * inv;
    }

    // --- load V chunk duplicated: Vsd[c][2s] ---
    {
        const float* Vb = g_V + ((size_t)b * CT_) + (size_t)cc * 32 * T_;
#pragma unroll
        for (int q = 0; q < 2; q++) {
            int l = tid + q * 256;
            int c = l >> 4, s4 = l & 15;
            float4 v = *(const float4*)&Vb[(size_t)c * T_ + s4 * 4];
            Vsd[c][s4 * 8 + 0] = v.x; Vsd[c][s4 * 8 + 1] = v.x;
            Vsd[c][s4 * 8 + 2] = v.y; Vsd[c][s4 * 8 + 3] = v.y;
            Vsd[c][s4 * 8 + 4] = v.z; Vsd[c][s4 * 8 + 5] = v.z;
            Vsd[c][s4 * 8 + 6] = v.w; Vsd[c][s4 * 8 + 7] = v.w;
        }
    }
    __syncthreads();

    // --- Fatt[c][t] = sum_s V[c][s] * A[t][s]; thread = (c = tid&31, 8 t's) ---
    int c  = tid & 31;
    int t0 = (tid >> 5) * 8;
    ull acc[4];
#pragma unroll
    for (int j = 0; j < 4; j++) acc[j] = 0ull;
#pragma unroll
    for (int s = 0; s < 64; s++) {
        ull vv = *(const ull*)&Vsd[c][2 * s];        // (V[c][s], V[c][s])
        const float4* ap = (const float4*)&Ast[s][t0];
        float4 a0 = ap[0], a1 = ap[1];
        fma2(acc[0], vv, ((const ull*)&a0)[0]);
        fma2(acc[1], vv, ((const ull*)&a0)[1]);
        fma2(acc[2], vv, ((const ull*)&a1)[0]);
        fma2(acc[3], vv, ((const ull*)&a1)[1]);
    }
    float* Fb = g_F + ((size_t)b * CT_) + (size_t)(cc * 32 + c) * T_ + t0;
    float r[8];
#pragma unroll
    for (int j = 0; j < 4; j++) unpack2(r[2 * j], r[2 * j + 1], acc[j]);
    *(float4*)&Fb[0] = make_float4(r[0], r[1], r[2], r[3]);
    *(float4*)&Fb[4] = make_float4(r[4], r[5], r[6], r[7]);
}

// ---------------- 5) bilinear upsample + blend, float4 I/O, descending plane order ---------
__global__ void upsample_blend_kernel(const float* __restrict__ Frgb,
                                      const float* __restrict__ alphap,
                                      float* __restrict__ out) {
    int plane = (B_ * C_ - 1) - blockIdx.x;
    __shared__ float Fs[64];
    __shared__ int   i0s[64];
    __shared__ int   i1s[64];
    __shared__ float fs[64];
    int tid = threadIdx.x;
    if (tid < 64) {
        Fs[tid] = g_F[(size_t)plane * T_ + tid];
        float s  = (tid + 0.5f) * 0.125f - 0.5f;
        float fl = floorf(s);
        int   i0 = (int)fl;
        fs[tid]  = s - fl;
        i0s[tid] = i0 < 0 ? 0 : i0;
        i1s[tid] = (i0 + 1) > 7 ? 7 : (i0 + 1);
    }
    __syncthreads();
    float alpha = *alphap;
    float beta  = 1.0f - alpha;
    const float4* rp = (const float4*)(Frgb + (size_t)plane * (HW_ * HW_));
    float4*       op = (float4*)(out  + (size_t)plane * (HW_ * HW_));
#pragma unroll
    for (int q = 0; q < 4; q++) {
        int i4 = tid + q * 256;
        int h  = i4 >> 4;
        int w0 = (i4 & 15) * 4;
        int   y0 = i0s[h], y1 = i1s[h]; float fy = fs[h];
        float4 r = rp[i4];
        float res[4];
#pragma unroll
        for (int j = 0; j < 4; j++) {
            int w = w0 + j;
            int   x0 = i0s[w], x1 = i1s[w]; float fx = fs[w];
            float v00 = Fs[y0 * 8 + x0], v01 = Fs[y0 * 8 + x1];
            float v10 = Fs[y1 * 8 + x0], v11 = Fs[y1 * 8 + x1];
            float top = v00 + fx * (v01 - v00);
            float bot = v10 + fx * (v11 - v10);
            res[j] = top + fy * (bot - top);
        }
        float4 o;
        o.x = alpha * res[0] + beta * r.x;
        o.y = alpha * res[1] + beta * r.y;
        o.z = alpha * res[2] + beta * r.z;
        o.w = alpha * res[3] + beta * r.w;
        op[i4] = o;
    }
}

// ---------------- launch ----------------
extern "C" void kernel_launch(void* const* d_in, const int* in_sizes, int n_in,
                              void* d_out, int out_size) {
    const float* Frgb  = (const float*)d_in[0];
    const float* Fd    = (const float*)d_in[1];
    const float* Wq    = (const float*)d_in[2];
    const float* bq    = (const float*)d_in[3];
    const float* Wk    = (const float*)d_in[4];
    const float* bk    = (const float*)d_in[5];
    const float* Wv    = (const float*)d_in[6];
    const float* bv    = (const float*)d_in[7];
    const float* alpha = (const float*)d_in[8];
    float* out = (float*)d_out;

    pool_kernel<<<2 * B_ * C_, 128>>>(Frgb, Fd);
    qkv_kernel<<<dim3(B_, 4, 3), 256>>>(Wq, bq, Wk, bk, Wv, bv);
    attn_partial_kernel<<<dim3(B_, 4), 256>>>();
    softmax_fatt_kernel<<<dim3(B_, 8), 256>>>();
    upsample_blend_kernel<<<B_ * C_, 256>>>(Frgb, alpha, out);
}

// round 5
// speedup vs baseline: 1.1056x; 1.1056x over previous
#include <cuda_runtime.h>
#include <cuda_bf16.h>

#define B_  32
#define C_  256
#define HW_ 64
#define AS_ 8
#define T_  64    // AS*AS
#define CT_ (C_ * T_)

// ---------------- scratch (device globals; batch-major [b][c][t]) ----------------
__device__ float g_PR[B_ * CT_];
__device__ float g_PD[B_ * CT_];
__device__ float g_M [C_ * C_];              // Wq^T Wk
__device__ float g_E [B_ * CT_];             // M * D
__device__ float g_V [B_ * CT_];
__device__ float g_g [B_ * T_];              // (Wk^T bq)^T D  (softmax s-offset)
__device__ float g_Apart[4 * B_ * T_ * T_];  // 4 c-slices of 64
__device__ float g_A [B_ * T_ * T_];
__device__ float g_F [B_ * CT_];

// ---------------- 1) 8x8 avg pool (F_d first, F_rgb last for L2 residency) ----------------
__global__ void pool_kernel(const float* __restrict__ Frgb, const float* __restrict__ Fd) {
    int bid   = blockIdx.x;
    int which = bid >> 13;            // 0: F_d first, 1: F_rgb last (stays in L2 for blend)
    int plane = bid & 8191;
    const float* src = (which ? Frgb : Fd) + (size_t)plane * (HW_ * HW_);
    float* dst = (which ? g_PR : g_PD) + (size_t)plane * T_;

    __shared__ float part[128];
    int t = threadIdx.x;
    int chunk = t & 15;
    int i     = t >> 4;
    const float4* p = (const float4*)src;
    float s = 0.f;
#pragma unroll
    for (int r = 0; r < 8; r++) {
        float4 v = p[(i * 8 + r) * 16 + chunk];
        s += (v.x + v.y) + (v.z + v.w);
    }
    part[t] = s;
    __syncthreads();
    if (t < 64) {
        int pi = t >> 3, pj = t & 7;
        dst[t] = (part[pi * 16 + 2 * pj] + part[pi * 16 + 2 * pj + 1]) * (1.0f / 64.0f);
    }
}

// ---------------- 2) M = Wq^T Wk  (M[c][d] = sum_o Wq[o][c] Wk[o][d]) ----------------
// grid (8,8), 256 threads, 2x2 micro-tile, K=256 in chunks of 32.
__global__ void prep_kernel(const float* __restrict__ Wq, const float* __restrict__ Wk) {
    int c0 = blockIdx.x * 32;
    int d0 = blockIdx.y * 32;
    __shared__ float Aq[32][33];   // [o][c]
    __shared__ float Ak[32][33];   // [o][d]
    int tid = threadIdx.x;
    int mi = (tid >> 4) * 2;       // 16 groups * 2
    int ni = (tid & 15) * 2;
    float acc[2][2] = {};
    for (int o0 = 0; o0 < C_; o0 += 32) {
        int row = tid >> 3, c4 = tid & 7;                 // 256 threads = 32 rows x 8 float4
        float4 q = *(const float4*)&Wq[(o0 + row) * C_ + c0 + c4 * 4];
        Aq[row][c4 * 4 + 0] = q.x; Aq[row][c4 * 4 + 1] = q.y;
        Aq[row][c4 * 4 + 2] = q.z; Aq[row][c4 * 4 + 3] = q.w;
        float4 k = *(const float4*)&Wk[(o0 + row) * C_ + d0 + c4 * 4];
        Ak[row][c4 * 4 + 0] = k.x; Ak[row][c4 * 4 + 1] = k.y;
        Ak[row][c4 * 4 + 2] = k.z; Ak[row][c4 * 4 + 3] = k.w;
        __syncthreads();
#pragma unroll
        for (int k2 = 0; k2 < 32; k2++) {
            float a0 = Aq[k2][mi], a1 = Aq[k2][mi + 1];
            float b0 = Ak[k2][ni], b1 = Ak[k2][ni + 1];
            acc[0][0] = fmaf(a0, b0, acc[0][0]); acc[0][1] = fmaf(a0, b1, acc[0][1]);
            acc[1][0] = fmaf(a1, b0, acc[1][0]); acc[1][1] = fmaf(a1, b1, acc[1][1]);
        }
        __syncthreads();
    }
#pragma unroll
    for (int i = 0; i < 2; i++)
#pragma unroll
        for (int j = 0; j < 2; j++)
            g_M[(size_t)(c0 + mi + i) * C_ + d0 + ni + j] = acc[i][j];
}

// ---------------- 3) g[b][s] = sum_c (Wk^T bq)[c] * D[b][c][s] ----------------
// grid B_, 256 threads (u computed redundantly per block; Wk is L2-hot).
__global__ void gvec_kernel(const float* __restrict__ Wk, const float* __restrict__ bq) {
    __shared__ float u[C_];
    int b = blockIdx.x, tid = threadIdx.x;
    float s = 0.f;
    for (int o = 0; o < C_; o++) s = fmaf(bq[o], Wk[(size_t)o * C_ + tid], s);
    u[tid] = s;
    __syncthreads();
    if (tid < T_) {
        const float* Db = g_PD + (size_t)b * CT_;
        float g = 0.f;
        for (int c = 0; c < C_; c++) g = fmaf(u[c], Db[(size_t)c * T_ + tid], g);
        g_g[b * T_ + tid] = g;
    }
}

// ---------------- 4) E = M*D and V = Wv*D + bv (R1-style scalar GEMM) ----------------
// grid (B, 4 m-tiles of 64, 2), 256 threads, 4x4 micro-tile.
__global__ void ev_kernel(const float* __restrict__ Wv, const float* __restrict__ bv) {
    int b  = blockIdx.x;
    int o0 = blockIdx.y * 64;
    int z  = blockIdx.z;
    const float* W  = (z == 0) ? g_M : Wv;
    float*       Out = (z == 0) ? g_E : g_V;

    __shared__ float Ws[64][33];
    __shared__ float Xs[32][64];

    int tid = threadIdx.x;
    int m0 = (tid >> 4) * 4;
    int n0 = (tid & 15) * 4;
    float acc[4][4] = {};
    const float* Pb = g_PD + ((size_t)b * CT_);

    for (int kc = 0; kc < C_; kc += 32) {
#pragma unroll
        for (int q = 0; q < 2; q++) {
            int l = tid + q * 256;
            int row = l >> 3, c4 = l & 7;
            float4 v = *(const float4*)&W[(size_t)(o0 + row) * C_ + kc + c4 * 4];
            Ws[row][c4 * 4 + 0] = v.x; Ws[row][c4 * 4 + 1] = v.y;
            Ws[row][c4 * 4 + 2] = v.z; Ws[row][c4 * 4 + 3] = v.w;
        }
#pragma unroll
        for (int q = 0; q < 2; q++) {
            int l = tid + q * 256;
            int row = l >> 4, c4 = l & 15;
            *(float4*)&Xs[row][c4 * 4] = *(const float4*)&Pb[(size_t)(kc + row) * T_ + c4 * 4];
        }
        __syncthreads();
#pragma unroll
        for (int k = 0; k < 32; k++) {
            float a0 = Ws[m0 + 0][k], a1 = Ws[m0 + 1][k], a2 = Ws[m0 + 2][k], a3 = Ws[m0 + 3][k];
            float4 bv4 = *(const float4*)&Xs[k][n0];
            float bb[4] = {bv4.x, bv4.y, bv4.z, bv4.w};
#pragma unroll
            for (int j = 0; j < 4; j++) {
                acc[0][j] = fmaf(a0, bb[j], acc[0][j]);
                acc[1][j] = fmaf(a1, bb[j], acc[1][j]);
                acc[2][j] = fmaf(a2, bb[j], acc[2][j]);
                acc[3][j] = fmaf(a3, bb[j], acc[3][j]);
            }
        }
        __syncthreads();
    }

    float* Ob = Out + ((size_t)b * CT_);
#pragma unroll
    for (int i = 0; i < 4; i++) {
        float bbv = (z == 0) ? 0.f : bv[o0 + m0 + i];
        *(float4*)&Ob[(size_t)(o0 + m0 + i) * T_ + n0] =
            make_float4(acc[i][0] + bbv, acc[i][1] + bbv, acc[i][2] + bbv, acc[i][3] + bbv);
    }
}

// ---------------- 5) partial A: A_p[b][t][s] = sum_{c in 64-slice} R[b][c][t] E[b][c][s] ----
// grid (B, 4), 256 threads, scalar 4x4 micro-tile.
__global__ void attn_partial_kernel() {
    int b  = blockIdx.x;
    int c0 = blockIdx.y * 64;
    __shared__ float Rs[64][64];
    __shared__ float Es[64][64];
    int tid = threadIdx.x;
    const float* Rb = g_PR + ((size_t)b * CT_) + (size_t)c0 * T_;
    const float* Eb = g_E  + ((size_t)b * CT_) + (size_t)c0 * T_;
#pragma unroll
    for (int q = 0; q < 4; q++) {
        int l = tid + q * 256;
        int row = l >> 4, c4 = l & 15;
        *(float4*)&Rs[row][c4 * 4] = *(const float4*)&Rb[(size_t)row * T_ + c4 * 4];
        *(float4*)&Es[row][c4 * 4] = *(const float4*)&Eb[(size_t)row * T_ + c4 * 4];
    }
    __syncthreads();
    int m0 = (tid >> 4) * 4;   // t
    int n0 = (tid & 15) * 4;   // s
    float acc[4][4] = {};
#pragma unroll
    for (int k = 0; k < 64; k++) {
        float4 av = *(const float4*)&Rs[k][m0];
        float4 bv4 = *(const float4*)&Es[k][n0];
        float aa[4] = {av.x, av.y, av.z, av.w};
        float bb[4] = {bv4.x, bv4.y, bv4.z, bv4.w};
#pragma unroll
        for (int i = 0; i < 4; i++)
#pragma unroll
            for (int j = 0; j < 4; j++)
                acc[i][j] = fmaf(aa[i], bb[j], acc[i][j]);
    }
    float* Ap = g_Apart + (((size_t)blockIdx.y * B_ + b) * (T_ * T_));
#pragma unroll
    for (int i = 0; i < 4; i++)
        *(float4*)&Ap[(m0 + i) * T_ + n0] =
            make_float4(acc[i][0], acc[i][1], acc[i][2], acc[i][3]);
}

// ---------------- 6) reduce 4 partials + g[s] + row softmax ----------------
// grid (B, 4): 16 rows per block, 256 threads (8 warps, 2 rows/warp).
__global__ void softmax_kernel() {
    int b  = blockIdx.x;
    int r0 = blockIdx.y * 16;
    int tid = threadIdx.x;
    int warp = tid >> 5, lane = tid & 31;
    float g0 = g_g[b * T_ + lane];
    float g1 = g_g[b * T_ + lane + 32];
#pragma unroll
    for (int rr = 0; rr < 2; rr++) {
        int r = r0 + warp * 2 + rr;
        size_t base = (size_t)b * (T_ * T_) + r * T_;
        float v0 = g0, v1 = g1;
#pragma unroll
        for (int p = 0; p < 4; p++) {
            size_t pb = ((size_t)p * B_) * (T_ * T_) + base;
            v0 += g_Apart[pb + lane];
            v1 += g_Apart[pb + lane + 32];
        }
        float m = fmaxf(v0, v1);
#pragma unroll
        for (int off = 16; off; off >>= 1) m = fmaxf(m, __shfl_xor_sync(0xffffffffu, m, off));
        float e0 = __expf(v0 - m), e1 = __expf(v1 - m);
        float s = e0 + e1;
#pragma unroll
        for (int off = 16; off; off >>= 1) s += __shfl_xor_sync(0xffffffffu, s, off);
        float inv = 1.0f / s;
        g_A[base + lane]      = e0 * inv;
        g_A[base + lane + 32] = e1 * inv;
    }
}

// ---------------- 7) Fatt[b][c][t] = sum_s V[b][c][s] * A[b][t][s] ----------------
// grid (B, 8 chunks of 32 channels), 256 threads.
__global__ void fatt_kernel() {
    int b = blockIdx.x, cc = blockIdx.y;
    __shared__ float As[64][68];
    __shared__ float Vs[32][64];
    int tid = threadIdx.x;
    const float* Ab = g_A + ((size_t)b * T_ * T_);
#pragma unroll
    for (int q = 0; q < 4; q++) {
        int l = tid + q * 256;
        int row = l >> 4, c4 = l & 15;
        *(float4*)&As[row][c4 * 4] = *(const float4*)&Ab[row * T_ + c4 * 4];
    }
    const float* Vb = g_V + ((size_t)b * CT_) + (size_t)cc * 32 * T_;
#pragma unroll
    for (int q = 0; q < 2; q++) {
        int l = tid + q * 256;
        int row = l >> 4, c4 = l & 15;
        *(float4*)&Vs[row][c4 * 4] = *(const float4*)&Vb[(size_t)row * T_ + c4 * 4];
    }
    __syncthreads();
    int cl = tid >> 3;
    int t0 = tid & 7;
    float acc[8] = {};
#pragma unroll
    for (int s4 = 0; s4 < 16; s4++) {
        float4 v = *(const float4*)&Vs[cl][s4 * 4];
#pragma unroll
        for (int j = 0; j < 8; j++) {
            float4 a = *(const float4*)&As[t0 + 8 * j][s4 * 4];
            acc[j] = fmaf(v.x, a.x, acc[j]);
            acc[j] = fmaf(v.y, a.y, acc[j]);
            acc[j] = fmaf(v.z, a.z, acc[j]);
            acc[j] = fmaf(v.w, a.w, acc[j]);
        }
    }
    float* Fb = g_F + ((size_t)b * CT_) + (size_t)(cc * 32 + cl) * T_;
#pragma unroll
    for (int j = 0; j < 8; j++) Fb[t0 + 8 * j] = acc[j];
}

// ---------------- 8) bilinear upsample + blend, float4 I/O, descending plane order ---------
__global__ void upsample_blend_kernel(const float* __restrict__ Frgb,
                                      const float* __restrict__ alphap,
                                      float* __restrict__ out) {
    int plane = (B_ * C_ - 1) - blockIdx.x;
    __shared__ float Fs[64];
    __shared__ int   i0s[64];
    __shared__ int   i1s[64];
    __shared__ float fs[64];
    int tid = threadIdx.x;
    if (tid < 64) {
        Fs[tid] = g_F[(size_t)plane * T_ + tid];
        float s  = (tid + 0.5f) * 0.125f - 0.5f;
        float fl = floorf(s);
        int   i0 = (int)fl;
        fs[tid]  = s - fl;
        i0s[tid] = i0 < 0 ? 0 : i0;
        i1s[tid] = (i0 + 1) > 7 ? 7 : (i0 + 1);
    }
    __syncthreads();
    float alpha = *alphap;
    float beta  = 1.0f - alpha;
    const float4* rp = (const float4*)(Frgb + (size_t)plane * (HW_ * HW_));
    float4*       op = (float4*)(out  + (size_t)plane * (HW_ * HW_));
#pragma unroll
    for (int q = 0; q < 4; q++) {
        int i4 = tid + q * 256;
        int h  = i4 >> 4;
        int w0 = (i4 & 15) * 4;
        int   y0 = i0s[h], y1 = i1s[h]; float fy = fs[h];
        float4 r = rp[i4];
        float res[4];
#pragma unroll
        for (int j = 0; j < 4; j++) {
            int w = w0 + j;
            int   x0 = i0s[w], x1 = i1s[w]; float fx = fs[w];
            float v00 = Fs[y0 * 8 + x0], v01 = Fs[y0 * 8 + x1];
            float v10 = Fs[y1 * 8 + x0], v11 = Fs[y1 * 8 + x1];
            float top = v00 + fx * (v01 - v00);
            float bot = v10 + fx * (v11 - v10);
            res[j] = top + fy * (bot - top);
        }
        float4 o;
        o.x = alpha * res[0] + beta * r.x;
        o.y = alpha * res[1] + beta * r.y;
        o.z = alpha * res[2] + beta * r.z;
        o.w = alpha * res[3] + beta * r.w;
        op[i4] = o;
    }
}

// ---------------- launch ----------------
extern "C" void kernel_launch(void* const* d_in, const int* in_sizes, int n_in,
                              void* d_out, int out_size) {
    const float* Frgb  = (const float*)d_in[0];
    const float* Fd    = (const float*)d_in[1];
    const float* Wq    = (const float*)d_in[2];
    const float* bq    = (const float*)d_in[3];
    const float* Wk    = (const float*)d_in[4];
    const float* bk    = (const float*)d_in[5];
    const float* Wv    = (const float*)d_in[6];
    const float* bv    = (const float*)d_in[7];
    const float* alpha = (const float*)d_in[8];
    float* out = (float*)d_out;
    (void)bk;  // cancels under softmax (constant in s)

    pool_kernel<<<2 * B_ * C_, 128>>>(Frgb, Fd);
    prep_kernel<<<dim3(8, 8), 256>>>(Wq, Wk);
    gvec_kernel<<<B_, 256>>>(Wk, bq);
    ev_kernel<<<dim3(B_, 4, 2), 256>>>(Wv, bv);
    attn_partial_kernel<<<dim3(B_, 4), 256>>>();
    softmax_kernel<<<dim3(B_, 4), 256>>>();
    fatt_kernel<<<dim3(B_, 8), 256>>>();
    upsample_blend_kernel<<<B_ * C_, 256>>>(Frgb, alpha, out);
}

// round 6
// speedup vs baseline: 1.2862x; 1.1634x over previous
#include <cuda_runtime.h>
#include <cuda_bf16.h>

#define B_  32
#define C_  256
#define HW_ 64
#define AS_ 8
#define T_  64    // AS*AS
#define CT_ (C_ * T_)

// ---------------- scratch (device globals; batch-major [b][c][t]) ----------------
__device__ float g_PR[B_ * CT_];
__device__ float g_PD[B_ * CT_];
__device__ float g_Q [B_ * CT_];
__device__ float g_K [B_ * CT_];
__device__ float g_V [B_ * CT_];
__device__ float g_Apart[4 * B_ * T_ * T_];  // 4 c-slices of 64
__device__ float g_A [B_ * T_ * T_];
__device__ float g_F [B_ * CT_];

// ---------------- 1) 8x8 avg pool (F_d first, F_rgb last for L2 residency) ----------------
// grid: 2*B*C blocks, 128 threads; one 64x64 plane each.
__global__ void pool_kernel(const float* __restrict__ Frgb, const float* __restrict__ Fd) {
    int bid   = blockIdx.x;
    int which = bid >> 13;            // 0: F_d first, 1: F_rgb last (stays in L2 for blend)
    int plane = bid & 8191;
    const float* src = (which ? Frgb : Fd) + (size_t)plane * (HW_ * HW_);
    float* dst = (which ? g_PR : g_PD) + (size_t)plane * T_;

    __shared__ float part[128];
    int t = threadIdx.x;
    int chunk = t & 15;
    int i     = t >> 4;
    const float4* p = (const float4*)src;
    float s = 0.f;
#pragma unroll
    for (int r = 0; r < 8; r++) {
        float4 v = p[(i * 8 + r) * 16 + chunk];
        s += (v.x + v.y) + (v.z + v.w);
    }
    part[t] = s;
    __syncthreads();
    if (t < 64) {
        int pi = t >> 3, pj = t & 7;
        dst[t] = (part[pi * 16 + 2 * pj] + part[pi * 16 + 2 * pj + 1]) * (1.0f / 64.0f);
    }
}

// ---------------- 2) QKV: Out[b][o][t] = sum_c W[o][c] * P[b][c][t] + bias[o] ----------------
// grid (B, 8 m-tiles of 32, 3), 128 threads, 4m x 4n micro-tile. High block count for occupancy.
__global__ void qkv_kernel(const float* __restrict__ Wq, const float* __restrict__ bq,
                           const float* __restrict__ Wk, const float* __restrict__ bk,
                           const float* __restrict__ Wv, const float* __restrict__ bv) {
    int b  = blockIdx.x;
    int o0 = blockIdx.y * 32;
    int z  = blockIdx.z;
    const float* W; const float* bias; const float* P; float* Out;
    if (z == 0)      { W = Wq; bias = bq; P = g_PR; Out = g_Q; }
    else if (z == 1) { W = Wk; bias = bk; P = g_PD; Out = g_K; }
    else             { W = Wv; bias = bv; P = g_PD; Out = g_V; }

    __shared__ float Ws[32][33];   // [m][k] padded
    __shared__ float Xs[32][64];   // [k][t]

    int tid = threadIdx.x;         // 128
    int m0 = (tid >> 4) * 4;       // 8 m-groups * 4 = 32
    int n0 = (tid & 15) * 4;       // 16 n-groups * 4 = 64
    float acc[4][4] = {};
    const float* Pb = P + ((size_t)b * CT_);

    for (int kc = 0; kc < C_; kc += 32) {
        // W tile [32m][32k]: 256 float4, 128 threads x 2
#pragma unroll
        for (int q = 0; q < 2; q++) {
            int l = tid + q * 128;
            int row = l >> 3, c4 = l & 7;
            float4 v = *(const float4*)&W[(size_t)(o0 + row) * C_ + kc + c4 * 4];
            Ws[row][c4 * 4 + 0] = v.x; Ws[row][c4 * 4 + 1] = v.y;
            Ws[row][c4 * 4 + 2] = v.z; Ws[row][c4 * 4 + 3] = v.w;
        }
        // X tile [32k][64t]: 512 float4, 128 threads x 4
#pragma unroll
        for (int q = 0; q < 4; q++) {
            int l = tid + q * 128;
            int row = l >> 4, c4 = l & 15;
            *(float4*)&Xs[row][c4 * 4] = *(const float4*)&Pb[(size_t)(kc + row) * T_ + c4 * 4];
        }
        __syncthreads();
#pragma unroll
        for (int k = 0; k < 32; k++) {
            float a0 = Ws[m0 + 0][k], a1 = Ws[m0 + 1][k], a2 = Ws[m0 + 2][k], a3 = Ws[m0 + 3][k];
            float4 bv4 = *(const float4*)&Xs[k][n0];
            float bb[4] = {bv4.x, bv4.y, bv4.z, bv4.w};
#pragma unroll
            for (int j = 0; j < 4; j++) {
                acc[0][j] = fmaf(a0, bb[j], acc[0][j]);
                acc[1][j] = fmaf(a1, bb[j], acc[1][j]);
                acc[2][j] = fmaf(a2, bb[j], acc[2][j]);
                acc[3][j] = fmaf(a3, bb[j], acc[3][j]);
            }
        }
        __syncthreads();
    }

    float* Ob = Out + ((size_t)b * CT_);
#pragma unroll
    for (int i = 0; i < 4; i++) {
        float bbv = bias[o0 + m0 + i];
        *(float4*)&Ob[(size_t)(o0 + m0 + i) * T_ + n0] =
            make_float4(acc[i][0] + bbv, acc[i][1] + bbv, acc[i][2] + bbv, acc[i][3] + bbv);
    }
}

// ---------------- 3) partial A: A_p[b][t][s] = sum_{c in 64-slice} Q[b][c][t] K[b][c][s] ----
// grid (B, 4), 256 threads, scalar 4x4 micro-tile.
__global__ void attn_partial_kernel() {
    int b  = blockIdx.x;
    int c0 = blockIdx.y * 64;
    __shared__ float Qs[64][64];
    __shared__ float Ks[64][64];
    int tid = threadIdx.x;
    const float* Qb = g_Q + ((size_t)b * CT_) + (size_t)c0 * T_;
    const float* Kb = g_K + ((size_t)b * CT_) + (size_t)c0 * T_;
#pragma unroll
    for (int q = 0; q < 4; q++) {
        int l = tid + q * 256;
        int row = l >> 4, c4 = l & 15;
        *(float4*)&Qs[row][c4 * 4] = *(const float4*)&Qb[(size_t)row * T_ + c4 * 4];
        *(float4*)&Ks[row][c4 * 4] = *(const float4*)&Kb[(size_t)row * T_ + c4 * 4];
    }
    __syncthreads();
    int m0 = (tid >> 4) * 4;   // t
    int n0 = (tid & 15) * 4;   // s
    float acc[4][4] = {};
#pragma unroll
    for (int k = 0; k < 64; k++) {
        float4 av  = *(const float4*)&Qs[k][m0];
        float4 bv4 = *(const float4*)&Ks[k][n0];
        float aa[4] = {av.x, av.y, av.z, av.w};
        float bb[4] = {bv4.x, bv4.y, bv4.z, bv4.w};
#pragma unroll
        for (int i = 0; i < 4; i++)
#pragma unroll
            for (int j = 0; j < 4; j++)
                acc[i][j] = fmaf(aa[i], bb[j], acc[i][j]);
    }
    float* Ap = g_Apart + (((size_t)blockIdx.y * B_ + b) * (T_ * T_));
#pragma unroll
    for (int i = 0; i < 4; i++)
        *(float4*)&Ap[(m0 + i) * T_ + n0] =
            make_float4(acc[i][0], acc[i][1], acc[i][2], acc[i][3]);
}

// ---------------- 4) reduce 4 partials + row softmax ----------------
// grid (B, 4): 16 rows per block, 256 threads (8 warps, 2 rows/warp).
__global__ void softmax_kernel() {
    int b  = blockIdx.x;
    int r0 = blockIdx.y * 16;
    int tid = threadIdx.x;
    int warp = tid >> 5, lane = tid & 31;
#pragma unroll
    for (int rr = 0; rr < 2; rr++) {
        int r = r0 + warp * 2 + rr;
        size_t base = (size_t)b * (T_ * T_) + r * T_;
        float v0 = 0.f, v1 = 0.f;
#pragma unroll
        for (int p = 0; p < 4; p++) {
            size_t pb = ((size_t)p * B_) * (T_ * T_) + base;
            v0 += g_Apart[pb + lane];
            v1 += g_Apart[pb + lane + 32];
        }
        float m = fmaxf(v0, v1);
#pragma unroll
        for (int off = 16; off; off >>= 1) m = fmaxf(m, __shfl_xor_sync(0xffffffffu, m, off));
        float e0 = __expf(v0 - m), e1 = __expf(v1 - m);
        float s = e0 + e1;
#pragma unroll
        for (int off = 16; off; off >>= 1) s += __shfl_xor_sync(0xffffffffu, s, off);
        float inv = 1.0f / s;
        g_A[base + lane]      = e0 * inv;
        g_A[base + lane + 32] = e1 * inv;
    }
}

// ---------------- 5) Fatt[b][c][t] = sum_s V[b][c][s] * A[b][t][s] ----------------
// grid (B, 8 chunks of 32 channels), 256 threads.
__global__ void fatt_kernel() {
    int b = blockIdx.x, cc = blockIdx.y;
    __shared__ float As[64][68];
    __shared__ float Vs[32][64];
    int tid = threadIdx.x;
    const float* Ab = g_A + ((size_t)b * T_ * T_);
#pragma unroll
    for (int q = 0; q < 4; q++) {
        int l = tid + q * 256;
        int row = l >> 4, c4 = l & 15;
        *(float4*)&As[row][c4 * 4] = *(const float4*)&Ab[row * T_ + c4 * 4];
    }
    const float* Vb = g_V + ((size_t)b * CT_) + (size_t)cc * 32 * T_;
#pragma unroll
    for (int q = 0; q < 2; q++) {
        int l = tid + q * 256;
        int row = l >> 4, c4 = l & 15;
        *(float4*)&Vs[row][c4 * 4] = *(const float4*)&Vb[(size_t)row * T_ + c4 * 4];
    }
    __syncthreads();
    int cl = tid >> 3;
    int t0 = tid & 7;
    float acc[8] = {};
#pragma unroll
    for (int s4 = 0; s4 < 16; s4++) {
        float4 v = *(const float4*)&Vs[cl][s4 * 4];
#pragma unroll
        for (int j = 0; j < 8; j++) {
            float4 a = *(const float4*)&As[t0 + 8 * j][s4 * 4];
            acc[j] = fmaf(v.x, a.x, acc[j]);
            acc[j] = fmaf(v.y, a.y, acc[j]);
            acc[j] = fmaf(v.z, a.z, acc[j]);
            acc[j] = fmaf(v.w, a.w, acc[j]);
        }
    }
    float* Fb = g_F + ((size_t)b * CT_) + (size_t)(cc * 32 + cl) * T_;
#pragma unroll
    for (int j = 0; j < 8; j++) Fb[t0 + 8 * j] = acc[j];
}

// ---------------- 6) bilinear upsample + blend, float4 I/O, descending plane order ---------
__global__ void upsample_blend_kernel(const float* __restrict__ Frgb,
                                      const float* __restrict__ alphap,
                                      float* __restrict__ out) {
    int plane = (B_ * C_ - 1) - blockIdx.x;   // reverse: F_rgb tail still in L2
    __shared__ float Fs[64];
    __shared__ int   i0s[64];
    __shared__ int   i1s[64];
    __shared__ float fs[64];
    int tid = threadIdx.x;
    if (tid < 64) {
        Fs[tid] = g_F[(size_t)plane * T_ + tid];
        float s  = (tid + 0.5f) * 0.125f - 0.5f;
        float fl = floorf(s);
        int   i0 = (int)fl;
        fs[tid]  = s - fl;
        i0s[tid] = i0 < 0 ? 0 : i0;
        i1s[tid] = (i0 + 1) > 7 ? 7 : (i0 + 1);
    }
    __syncthreads();
    float alpha = *alphap;
    float beta  = 1.0f - alpha;
    const float4* rp = (const float4*)(Frgb + (size_t)plane * (HW_ * HW_));
    float4*       op = (float4*)(out  + (size_t)plane * (HW_ * HW_));
#pragma unroll
    for (int q = 0; q < 4; q++) {
        int i4 = tid + q * 256;
        int h  = i4 >> 4;
        int w0 = (i4 & 15) * 4;
        int   y0 = i0s[h], y1 = i1s[h]; float fy = fs[h];
        float4 r = rp[i4];
        float res[4];
#pragma unroll
        for (int j = 0; j < 4; j++) {
            int w = w0 + j;
            int   x0 = i0s[w], x1 = i1s[w]; float fx = fs[w];
            float v00 = Fs[y0 * 8 + x0], v01 = Fs[y0 * 8 + x1];
            float v10 = Fs[y1 * 8 + x0], v11 = Fs[y1 * 8 + x1];
            float top = v00 + fx * (v01 - v00);
            float bot = v10 + fx * (v11 - v10);
            res[j] = top + fy * (bot - top);
        }
        float4 o;
        o.x = alpha * res[0] + beta * r.x;
        o.y = alpha * res[1] + beta * r.y;
        o.z = alpha * res[2] + beta * r.z;
        o.w = alpha * res[3] + beta * r.w;
        op[i4] = o;
    }
}

// ---------------- launch ----------------
extern "C" void kernel_launch(void* const* d_in, const int* in_sizes, int n_in,
                              void* d_out, int out_size) {
    const float* Frgb  = (const float*)d_in[0];
    const float* Fd    = (const float*)d_in[1];
    const float* Wq    = (const float*)d_in[2];
    const float* bq    = (const float*)d_in[3];
    const float* Wk    = (const float*)d_in[4];
    const float* bk    = (const float*)d_in[5];
    const float* Wv    = (const float*)d_in[6];
    const float* bv    = (const float*)d_in[7];
    const float* alpha = (const float*)d_in[8];
    float* out = (float*)d_out;

    pool_kernel<<<2 * B_ * C_, 128>>>(Frgb, Fd);
    qkv_kernel<<<dim3(B_, 8, 3), 128>>>(Wq, bq, Wk, bk, Wv, bv);
    attn_partial_kernel<<<dim3(B_, 4), 256>>>();
    softmax_kernel<<<dim3(B_, 4), 256>>>();
    fatt_kernel<<<dim3(B_, 8), 256>>>();
    upsample_blend_kernel<<<B_ * C_, 256>>>(Frgb, alpha, out);
}

// round 8
// speedup vs baseline: 1.2877x; 1.0011x over previous
#include <cuda_runtime.h>
#include <cuda_bf16.h>
#include <cstdint>

#define B_  32
#define C_  256
#define HW_ 64
#define AS_ 8
#define T_  64    // AS*AS
#define CT_ (C_ * T_)

typedef unsigned int u32;

// ---------------- scratch (device globals; batch-major [b][c][t]) ----------------
__device__ float g_PR[B_ * CT_];
__device__ float g_PD[B_ * CT_];
__device__ float g_Q [B_ * CT_];
__device__ float g_K [B_ * CT_];
__device__ float g_V [B_ * CT_];
__device__ float g_Apart[4 * B_ * T_ * T_];  // 4 c-slices of 64
__device__ float g_A [B_ * T_ * T_];
__device__ float g_F [B_ * CT_];

// ---------------- tf32 helpers ----------------
__device__ __forceinline__ void tf32_split(float x, u32& hi, u32& lo) {
    u32 h;
    asm("cvt.rna.tf32.f32 %0, %1;" : "=r"(h) : "f"(x));
    float lf = x - __uint_as_float(h);
    u32 l;
    asm("cvt.rna.tf32.f32 %0, %1;" : "=r"(l) : "f"(lf));
    hi = h; lo = l;
}
__device__ __forceinline__ void mma_tf32(float* c, const u32* a, const u32* b) {
    asm volatile(
        "mma.sync.aligned.m16n8k8.row.col.f32.tf32.tf32.f32 "
        "{%0,%1,%2,%3}, {%4,%5,%6,%7}, {%8,%9}, {%0,%1,%2,%3};"
        : "+f"(c[0]), "+f"(c[1]), "+f"(c[2]), "+f"(c[3])
        : "r"(a[0]), "r"(a[1]), "r"(a[2]), "r"(a[3]), "r"(b[0]), "r"(b[1]));
}

// ---------------- 1) 8x8 avg pool (F_d first, F_rgb last for L2 residency) ----------------
__global__ void pool_kernel(const float* __restrict__ Frgb, const float* __restrict__ Fd) {
    int bid   = blockIdx.x;
    int which = bid >> 13;
    int plane = bid & 8191;
    const float* src = (which ? Frgb : Fd) + (size_t)plane * (HW_ * HW_);
    float* dst = (which ? g_PR : g_PD) + (size_t)plane * T_;

    __shared__ float part[128];
    int t = threadIdx.x;
    int chunk = t & 15;
    int i     = t >> 4;
    const float4* p = (const float4*)src;
    float s = 0.f;
#pragma unroll
    for (int r = 0; r < 8; r++) {
        float4 v = p[(i * 8 + r) * 16 + chunk];
        s += (v.x + v.y) + (v.z + v.w);
    }
    part[t] = s;
    __syncthreads();
    if (t < 64) {
        int pi = t >> 3, pj = t & 7;
        dst[t] = (part[pi * 16 + 2 * pj] + part[pi * 16 + 2 * pj + 1]) * (1.0f / 64.0f);
    }
}

// ---------------- 2) QKV: 3xTF32 tensor-core GEMM ----------------
// Out[b][o][t] = sum_c W[o][c] * P[b][c][t] + bias[o]
// grid (B, 4 m-tiles of 64, 3), 128 threads (4 warps). Warp: 16m x 64n, k-chunks of 32.
__global__ void __launch_bounds__(128) qkv_kernel(
        const float* __restrict__ Wq, const float* __restrict__ bq,
        const float* __restrict__ Wk, const float* __restrict__ bk,
        const float* __restrict__ Wv, const float* __restrict__ bv) {
    int b  = blockIdx.x;
    int o0 = blockIdx.y * 64;
    int z  = blockIdx.z;
    const float* W; const float* bias; const float* P; float* Out;
    if (z == 0)      { W = Wq; bias = bq; P = g_PR; Out = g_Q; }
    else if (z == 1) { W = Wk; bias = bk; P = g_PD; Out = g_K; }
    else             { W = Wv; bias = bv; P = g_PD; Out = g_V; }

    __shared__ float Whi[64][36], Wlo[64][36];   // [m][k], pad 36: frag banks CF
    __shared__ float Phi[32][72], Plo[32][72];   // [k][n], pad 72: frag banks CF

    int tid  = threadIdx.x;
    int warp = tid >> 5;
    int lane = tid & 31;
    int g    = lane >> 2;      // 0..7
    int tig  = lane & 3;       // 0..3
    int mw   = warp * 16;      // warp m-base within block tile

    const float* Pb = P + ((size_t)b * CT_);

    float acc[8][4];
#pragma unroll
    for (int nt = 0; nt < 8; nt++)
#pragma unroll
        for (int j = 0; j < 4; j++) acc[nt][j] = 0.f;

    for (int kc = 0; kc < C_; kc += 32) {
        // load + split W tile [64m][32k]
#pragma unroll
        for (int q = 0; q < 4; q++) {
            int l = tid + q * 128;                 // 0..511 float4
            int row = l >> 3, c4 = l & 7;
            float4 v = *(const float4*)&W[(size_t)(o0 + row) * C_ + kc + c4 * 4];
            u32 h, lo;
            tf32_split(v.x, h, lo); Whi[row][c4*4+0] = __uint_as_float(h); Wlo[row][c4*4+0] = __uint_as_float(lo);
            tf32_split(v.y, h, lo); Whi[row][c4*4+1] = __uint_as_float(h); Wlo[row][c4*4+1] = __uint_as_float(lo);
            tf32_split(v.z, h, lo); Whi[row][c4*4+2] = __uint_as_float(h); Wlo[row][c4*4+2] = __uint_as_float(lo);
            tf32_split(v.w, h, lo); Whi[row][c4*4+3] = __uint_as_float(h); Wlo[row][c4*4+3] = __uint_as_float(lo);
        }
        // load + split P tile [32k][64n]
#pragma unroll
        for (int q = 0; q < 4; q++) {
            int l = tid + q * 128;                 // 0..511 float4
            int row = l >> 4, c4 = l & 15;
            float4 v = *(const float4*)&Pb[(size_t)(kc + row) * T_ + c4 * 4];
            u32 h, lo;
            tf32_split(v.x, h, lo); Phi[row][c4*4+0] = __uint_as_float(h); Plo[row][c4*4+0] = __uint_as_float(lo);
            tf32_split(v.y, h, lo); Phi[row][c4*4+1] = __uint_as_float(h); Plo[row][c4*4+1] = __uint_as_float(lo);
            tf32_split(v.z, h, lo); Phi[row][c4*4+2] = __uint_as_float(h); Plo[row][c4*4+2] = __uint_as_float(lo);
            tf32_split(v.w, h, lo); Phi[row][c4*4+3] = __uint_as_float(h); Plo[row][c4*4+3] = __uint_as_float(lo);
        }
        __syncthreads();
#pragma unroll
        for (int kk = 0; kk < 4; kk++) {
            int k0 = kk * 8;
            u32 ah[4], al[4];
            ah[0] = __float_as_uint(Whi[mw + g    ][k0 + tig    ]);
            ah[1] = __float_as_uint(Whi[mw + g + 8][k0 + tig    ]);
            ah[2] = __float_as_uint(Whi[mw + g    ][k0 + tig + 4]);
            ah[3] = __float_as_uint(Whi[mw + g + 8][k0 + tig + 4]);
            al[0] = __float_as_uint(Wlo[mw + g    ][k0 + tig    ]);
            al[1] = __float_as_uint(Wlo[mw + g + 8][k0 + tig    ]);
            al[2] = __float_as_uint(Wlo[mw + g    ][k0 + tig + 4]);
            al[3] = __float_as_uint(Wlo[mw + g + 8][k0 + tig + 4]);
#pragma unroll
            for (int nt = 0; nt < 8; nt++) {
                int n = nt * 8 + g;
                u32 bh[2], bl[2];
                bh[0] = __float_as_uint(Phi[k0 + tig    ][n]);
                bh[1] = __float_as_uint(Phi[k0 + tig + 4][n]);
                bl[0] = __float_as_uint(Plo[k0 + tig    ][n]);
                bl[1] = __float_as_uint(Plo[k0 + tig + 4][n]);
                mma_tf32(acc[nt], ah, bh);   // hi*hi
                mma_tf32(acc[nt], ah, bl);   // hi*lo
                mma_tf32(acc[nt], al, bh);   // lo*hi
            }
        }
        __syncthreads();
    }

    // epilogue: c0,c1 -> row (mw+g), cols 2tig,2tig+1; c2,c3 -> row (mw+g+8)
    float* Ob = Out + ((size_t)b * CT_);
    int mA = o0 + mw + g;
    int mB = mA + 8;
    float bA = bias[mA], bB = bias[mB];
#pragma unroll
    for (int nt = 0; nt < 8; nt++) {
        int col = nt * 8 + 2 * tig;
        *(float2*)&Ob[(size_t)mA * T_ + col] = make_float2(acc[nt][0] + bA, acc[nt][1] + bA);
        *(float2*)&Ob[(size_t)mB * T_ + col] = make_float2(acc[nt][2] + bB, acc[nt][3] + bB);
    }
}

// ---------------- 3) partial A: A_p[b][t][s] = sum_{c in 64-slice} Q[b][c][t] K[b][c][s] ----
// grid (B, 4), 256 threads, scalar 4x4 micro-tile.
__global__ void attn_partial_kernel() {
    int b  = blockIdx.x;
    int c0 = blockIdx.y * 64;
    __shared__ float Qs[64][64];
    __shared__ float Ks[64][64];
    int tid = threadIdx.x;
    const float* Qb = g_Q + ((size_t)b * CT_) + (size_t)c0 * T_;
    const float* Kb = g_K + ((size_t)b * CT_) + (size_t)c0 * T_;
#pragma unroll
    for (int q = 0; q < 4; q++) {
        int l = tid + q * 256;
        int row = l >> 4, c4 = l & 15;
        *(float4*)&Qs[row][c4 * 4] = *(const float4*)&Qb[(size_t)row * T_ + c4 * 4];
        *(float4*)&Ks[row][c4 * 4] = *(const float4*)&Kb[(size_t)row * T_ + c4 * 4];
    }
    __syncthreads();
    int m0 = (tid >> 4) * 4;   // t
    int n0 = (tid & 15) * 4;   // s
    float acc[4][4] = {};
#pragma unroll
    for (int k = 0; k < 64; k++) {
        float4 av  = *(const float4*)&Qs[k][m0];
        float4 bv4 = *(const float4*)&Ks[k][n0];
        float aa[4] = {av.x, av.y, av.z, av.w};
        float bb[4] = {bv4.x, bv4.y, bv4.z, bv4.w};
#pragma unroll
        for (int i = 0; i < 4; i++)
#pragma unroll
            for (int j = 0; j < 4; j++)
                acc[i][j] = fmaf(aa[i], bb[j], acc[i][j]);
    }
    float* Ap = g_Apart + (((size_t)blockIdx.y * B_ + b) * (T_ * T_));
#pragma unroll
    for (int i = 0; i < 4; i++)
        *(float4*)&Ap[(m0 + i) * T_ + n0] =
            make_float4(acc[i][0], acc[i][1], acc[i][2], acc[i][3]);
}

// ---------------- 4) reduce 4 partials + row softmax ----------------
__global__ void softmax_kernel() {
    int b  = blockIdx.x;
    int r0 = blockIdx.y * 16;
    int tid = threadIdx.x;
    int warp = tid >> 5, lane = tid & 31;
#pragma unroll
    for (int rr = 0; rr < 2; rr++) {
        int r = r0 + warp * 2 + rr;
        size_t base = (size_t)b * (T_ * T_) + r * T_;
        float v0 = 0.f, v1 = 0.f;
#pragma unroll
        for (int p = 0; p < 4; p++) {
            size_t pb = ((size_t)p * B_) * (T_ * T_) + base;
            v0 += g_Apart[pb + lane];
            v1 += g_Apart[pb + lane + 32];
        }
        float m = fmaxf(v0, v1);
#pragma unroll
        for (int off = 16; off; off >>= 1) m = fmaxf(m, __shfl_xor_sync(0xffffffffu, m, off));
        float e0 = __expf(v0 - m), e1 = __expf(v1 - m);
        float s = e0 + e1;
#pragma unroll
        for (int off = 16; off; off >>= 1) s += __shfl_xor_sync(0xffffffffu, s, off);
        float inv = 1.0f / s;
        g_A[base + lane]      = e0 * inv;
        g_A[base + lane + 32] = e1 * inv;
    }
}

// ---------------- 5) Fatt[b][c][t] = sum_s V[b][c][s] * A[b][t][s] ----------------
__global__ void fatt_kernel() {
    int b = blockIdx.x, cc = blockIdx.y;
    __shared__ float As[64][68];
    __shared__ float Vs[32][64];
    int tid = threadIdx.x;
    const float* Ab = g_A + ((size_t)b * T_ * T_);
#pragma unroll
    for (int q = 0; q < 4; q++) {
        int l = tid + q * 256;
        int row = l >> 4, c4 = l & 15;
        *(float4*)&As[row][c4 * 4] = *(const float4*)&Ab[row * T_ + c4 * 4];
    }
    const float* Vb = g_V + ((size_t)b * CT_) + (size_t)cc * 32 * T_;
#pragma unroll
    for (int q = 0; q < 2; q++) {
        int l = tid + q * 256;
        int row = l >> 4, c4 = l & 15;
        *(float4*)&Vs[row][c4 * 4] = *(const float4*)&Vb[(size_t)row * T_ + c4 * 4];
    }
    __syncthreads();
    int cl = tid >> 3;
    int t0 = tid & 7;
    float acc[8] = {};
#pragma unroll
    for (int s4 = 0; s4 < 16; s4++) {
        float4 v = *(const float4*)&Vs[cl][s4 * 4];
#pragma unroll
        for (int j = 0; j < 8; j++) {
            float4 a = *(const float4*)&As[t0 + 8 * j][s4 * 4];
            acc[j] = fmaf(v.x, a.x, acc[j]);
            acc[j] = fmaf(v.y, a.y, acc[j]);
            acc[j] = fmaf(v.z, a.z, acc[j]);
            acc[j] = fmaf(v.w, a.w, acc[j]);
        }
    }
    float* Fb = g_F + ((size_t)b * CT_) + (size_t)(cc * 32 + cl) * T_;
#pragma unroll
    for (int j = 0; j < 8; j++) Fb[t0 + 8 * j] = acc[j];
}

// ---------------- 6) bilinear upsample + blend, float4 I/O, descending plane order ---------
__global__ void upsample_blend_kernel(const float* __restrict__ Frgb,
                                      const float* __restrict__ alphap,
                                      float* __restrict__ out) {
    int plane = (B_ * C_ - 1) - blockIdx.x;
    __shared__ float Fs[64];
    __shared__ int   i0s[64];
    __shared__ int   i1s[64];
    __shared__ float fs[64];
    int tid = threadIdx.x;
    if (tid < 64) {
        Fs[tid] = g_F[(size_t)plane * T_ + tid];
        float s  = (tid + 0.5f) * 0.125f - 0.5f;
        float fl = floorf(s);
        int   i0 = (int)fl;
        fs[tid]  = s - fl;
        i0s[tid] = i0 < 0 ? 0 : i0;
        i1s[tid] = (i0 + 1) > 7 ? 7 : (i0 + 1);
    }
    __syncthreads();
    float alpha = *alphap;
    float beta  = 1.0f - alpha;
    const float4* rp = (const float4*)(Frgb + (size_t)plane * (HW_ * HW_));
    float4*       op = (float4*)(out  + (size_t)plane * (HW_ * HW_));
#pragma unroll
    for (int q = 0; q < 4; q++) {
        int i4 = tid + q * 256;
        int h  = i4 >> 4;
        int w0 = (i4 & 15) * 4;
        int   y0 = i0s[h], y1 = i1s[h]; float fy = fs[h];
        float4 r = rp[i4];
        float res[4];
#pragma unroll
        for (int j = 0; j < 4; j++) {
            int w = w0 + j;
            int   x0 = i0s[w], x1 = i1s[w]; float fx = fs[w];
            float v00 = Fs[y0 * 8 + x0], v01 = Fs[y0 * 8 + x1];
            float v10 = Fs[y1 * 8 + x0], v11 = Fs[y1 * 8 + x1];
            float top = v00 + fx * (v01 - v00);
            float bot = v10 + fx * (v11 - v10);
            res[j] = top + fy * (bot - top);
        }
        float4 o;
        o.x = alpha * res[0] + beta * r.x;
        o.y = alpha * res[1] + beta * r.y;
        o.z = alpha * res[2] + beta * r.z;
        o.w = alpha * res[3] + beta * r.w;
        op[i4] = o;
    }
}

// ---------------- launch ----------------
extern "C" void kernel_launch(void* const* d_in, const int* in_sizes, int n_in,
                              void* d_out, int out_size) {
    const float* Frgb  = (const float*)d_in[0];
    const float* Fd    = (const float*)d_in[1];
    const float* Wq    = (const float*)d_in[2];
    const float* bq    = (const float*)d_in[3];
    const float* Wk    = (const float*)d_in[4];
    const float* bk    = (const float*)d_in[5];
    const float* Wv    = (const float*)d_in[6];
    const float* bv    = (const float*)d_in[7];
    const float* alpha = (const float*)d_in[8];
    float* out = (float*)d_out;

    pool_kernel<<<2 * B_ * C_, 128>>>(Frgb, Fd);
    qkv_kernel<<<dim3(B_, 4, 3), 128>>>(Wq, bq, Wk, bk, Wv, bv);
    attn_partial_kernel<<<dim3(B_, 4), 256>>>();
    softmax_kernel<<<dim3(B_, 4), 256>>>();
    fatt_kernel<<<dim3(B_, 8), 256>>>();
    upsample_blend_kernel<<<B_ * C_, 256>>>(Frgb, alpha, out);
}